// round 2
// baseline (speedup 1.0000x reference)
#include <cuda_runtime.h>
#include <cstdint>

#define NBATCH 8
#define NLVL 5
#define NTOT 159882
#define NPAD 1024
#define FNPAD 8192
#define IMGSZ 800.0f
#define CLIPV 4.135166556742356f

__constant__ int c_h[NLVL]   = {200, 100, 50, 25, 13};
__constant__ int c_n[NLVL]   = {120000, 30000, 7500, 1875, 507};
__constant__ int c_off[NLVL] = {0, 120000, 150000, 157500, 159375};
__constant__ int c_k[NLVL]   = {1000, 1000, 1000, 1000, 507};

__device__ float    g_scores[NBATCH * NTOT];
__device__ float    g_kb[NBATCH][NLVL][NPAD][4];
__device__ unsigned g_kkey[NBATCH][NLVL][NPAD];
__device__ int      g_kcnt[NBATCH][NLVL];

typedef unsigned long long u64;

__device__ __forceinline__ unsigned fkey(float f) {
    unsigned u = __float_as_uint(f);
    return u ^ ((unsigned)((int)u >> 31) | 0x80000000u);
}

__device__ __forceinline__ int bscan(int v, int* ws, int tid, int* total) {
    int lane = tid & 31, wid = tid >> 5;
    int x = v;
#pragma unroll
    for (int o = 1; o < 32; o <<= 1) {
        int y = __shfl_up_sync(~0u, x, o);
        if (lane >= o) x += y;
    }
    if (lane == 31) ws[wid] = x;
    __syncthreads();
    if (wid == 0) {
        int y = ws[lane];
#pragma unroll
        for (int o = 1; o < 32; o <<= 1) {
            int z = __shfl_up_sync(~0u, y, o);
            if (lane >= o) y += z;
        }
        ws[lane] = y;
    }
    __syncthreads();
    int base = wid ? ws[wid - 1] : 0;
    int tot = ws[31];
    __syncthreads();
    *total = tot;
    return base + x - v;
}

__device__ __forceinline__ void bitonic_desc(u64* a, int n, int tid) {
    for (int sz = 2; sz <= n; sz <<= 1)
        for (int st = sz >> 1; st >= 1; st >>= 1) {
            __syncthreads();
            for (int t = tid; t < (n >> 1); t += 1024) {
                int i = t + (t & ~(st - 1));
                int j = i + st;
                u64 x = a[i], y = a[j];
                if (((i & sz) == 0) ? (x < y) : (x > y)) { a[i] = y; a[j] = x; }
            }
        }
    __syncthreads();
}

// ---- kernel 1: permute objectness (b,a,y,x) -> (b,(y*h+x)*3+a) flat -------
__global__ void permute_obj(const float* __restrict__ o0, const float* __restrict__ o1,
                            const float* __restrict__ o2, const float* __restrict__ o3,
                            const float* __restrict__ o4) {
    long long t = blockIdx.x * (long long)blockDim.x + threadIdx.x;
    if (t >= (long long)NBATCH * NTOT) return;
    int b = (int)(t / NTOT), r = (int)(t % NTOT);
    const float* op; int l;
    if (r < 120000)      { l = 0; op = o0; }
    else if (r < 150000) { l = 1; op = o1; }
    else if (r < 157500) { l = 2; op = o2; }
    else if (r < 159375) { l = 3; op = o3; }
    else                 { l = 4; op = o4; }
    int h = c_h[l], i = r - c_off[l];
    int a = i % 3, p = i / 3, y = p / h, x = p - y * h;
    g_scores[t] = op[((b * 3 + a) * h + y) * h + x];
}

// ---- kernel 2: per (batch,level): top-k -> sort -> decode -> NMS ----------
// smem layout bytes:
//  key64[1024]u64:0..8192 | hist[4096]u32:8192..24576 | 9 float[1024]:24576..61440
//  ukeyv:61440..65536 | keep:65536..69632 | misc(256 int):69632..70656
//  mask[1024*16]u64:70656..201728
#define SMEM2 201728

__global__ __launch_bounds__(1024, 1)
void rpn_level_kernel(const float* __restrict__ dl0, const float* __restrict__ dl1,
                      const float* __restrict__ dl2, const float* __restrict__ dl3,
                      const float* __restrict__ dl4, const float* __restrict__ anchors) {
    extern __shared__ unsigned char smraw[];
    u64*      key64 = (u64*)smraw;
    unsigned* hist  = (unsigned*)(smraw + 8192);
    float*    ox1   = (float*)(smraw + 24576);
    float*    oy1 = ox1 + NPAD, *ox2 = oy1 + NPAD, *oy2 = ox2 + NPAD, *oar = oy2 + NPAD;
    float*    ux1 = oar + NPAD, *uy1 = ux1 + NPAD, *ux2 = uy1 + NPAD, *uy2 = ux2 + NPAD;
    unsigned* ukeyv = (unsigned*)(uy2 + NPAD);
    unsigned* keep  = ukeyv + NPAD;
    int*      misc  = (int*)(keep + NPAD);
    u64*      mask  = (u64*)(smraw + 70656);

    int tid = threadIdx.x;
    int b = blockIdx.x / NLVL, l = blockIdx.x % NLVL;
    int n = c_n[l], kk = c_k[l], h = c_h[l];
    const float* sc = g_scores + b * NTOT + c_off[l];

    if (n == kk) {
        for (int j = tid; j < NPAD; j += 1024)
            key64[j] = (j < n) ? (((u64)fkey(sc[j]) << 32) | (unsigned)(~j)) : 0ULL;
        __syncthreads();
    } else {
        unsigned prefix = 0;
        int krem = kk;
        for (int pass = 0; pass < 3; pass++) {
            for (int q = tid; q < 4096; q += 1024) hist[q] = 0;
            __syncthreads();
            for (int q = tid; q < n; q += 1024) {
                unsigned u = fkey(sc[q]);
                unsigned bucket; bool ok;
                if (pass == 0)      { ok = true;                bucket = u >> 20; }
                else if (pass == 1) { ok = (u >> 20) == prefix; bucket = (u >> 8) & 0xFFFu; }
                else                { ok = (u >> 8) == prefix;  bucket = u & 0xFFu; }
                if (ok) atomicAdd(&hist[bucket], 1u);
            }
            __syncthreads();
            int nb = (pass == 2) ? 256 : 4096;
            int nchunk = nb >> 5;
            int* chunk = misc + 64;
            if (tid < nchunk) {
                unsigned s = 0;
                for (int q = 0; q < 32; q++) s += hist[tid * 32 + q];
                chunk[tid] = (int)s;
            }
            __syncthreads();
            if (tid == 0) {
                int acc = 0, c;
                for (c = nchunk - 1; c > 0; c--) {
                    if (acc + chunk[c] >= krem) break;
                    acc += chunk[c];
                }
                int bsel = c * 32;
                for (int q = 31; q >= 0; q--) {
                    int hv = (int)hist[c * 32 + q];
                    if (acc + hv >= krem) { bsel = c * 32 + q; break; }
                    acc += hv;
                }
                misc[1] = bsel; misc[2] = krem - acc;
            }
            __syncthreads();
            int bsel = misc[1];
            krem = misc[2];
            prefix = (pass == 0) ? (unsigned)bsel
                                 : ((prefix << ((pass == 1) ? 12 : 8)) | (unsigned)bsel);
            __syncthreads();
        }
        unsigned T = prefix;
        if (tid == 0) misc[0] = 0;
        __syncthreads();
        for (int q = tid; q < n; q += 1024) {
            unsigned u = fkey(sc[q]);
            if (u >= T) {
                int pos = atomicAdd(&misc[0], 1);
                if (pos < NPAD) key64[pos] = ((u64)u << 32) | (unsigned)(~q);
            }
        }
        __syncthreads();
        int scnt = misc[0] < NPAD ? misc[0] : NPAD;
        for (int q = tid; q < NPAD; q += 1024)
            if (q >= scnt) key64[q] = 0ULL;
        __syncthreads();
    }

    bitonic_desc(key64, NPAD, tid);   // (logit desc, idx asc) == lax.top_k order

    float C = 4096.0f * (float)l;
    const float* dl = (l == 0) ? dl0 : (l == 1) ? dl1 : (l == 2) ? dl2 : (l == 3) ? dl3 : dl4;
    int h2 = h * h;
    int valid = 0;
    float cx1 = 0.f, cy1 = 0.f, cx2 = 0.f, cy2 = 0.f;
    unsigned sigbits = 0;
    if (tid < kk) {
        u64 e = key64[tid];
        unsigned idx = ~(unsigned)(e & 0xFFFFFFFFu);
        float logit = sc[idx];
        sigbits = __float_as_uint(__fdiv_rn(1.0f, 1.0f + expf(-logit)));
        int a = (int)(idx % 3u), p = (int)(idx / 3u);
        int y = p / h, x = p - y * h;
        int gi = c_off[l] + (int)idx;
        float ax1 = anchors[4 * gi], ay1 = anchors[4 * gi + 1];
        float ax2 = anchors[4 * gi + 2], ay2 = anchors[4 * gi + 3];
        float wa = ax2 - ax1, ha = ay2 - ay1;
        float cxa = ax1 + 0.5f * wa, cya = ay1 + 0.5f * ha;
        int dbase = ((b * 12 + a * 4) * h + y) * h + x;
        float dx = dl[dbase], dy = dl[dbase + h2];
        float dw = fminf(dl[dbase + 2 * h2], CLIPV);
        float dh = fminf(dl[dbase + 3 * h2], CLIPV);
        float cx = dx * wa + cxa, cy = dy * ha + cya;
        float pw = expf(dw) * wa, ph = expf(dh) * ha;
        cx1 = fminf(fmaxf(cx - 0.5f * pw, 0.0f), IMGSZ);
        cy1 = fminf(fmaxf(cy - 0.5f * ph, 0.0f), IMGSZ);
        cx2 = fminf(fmaxf(cx + 0.5f * pw, 0.0f), IMGSZ);
        cy2 = fminf(fmaxf(cy + 0.5f * ph, 0.0f), IMGSZ);
        valid = ((cx2 - cx1) >= 1e-3f && (cy2 - cy1) >= 1e-3f) ? 1 : 0;
    }
    __syncthreads();

    int nv;
    int vpos = bscan(valid, misc + 8, tid, &nv);
    if (valid) {
        float xo1 = cx1 + C, yo1 = cy1 + C, xo2 = cx2 + C, yo2 = cy2 + C;
        ox1[vpos] = xo1; oy1[vpos] = yo1; ox2[vpos] = xo2; oy2[vpos] = yo2;
        oar[vpos] = (xo2 - xo1) * (yo2 - yo1);
        ux1[vpos] = cx1; uy1[vpos] = cy1; ux2[vpos] = cx2; uy2[vpos] = cy2;
        ukeyv[vpos] = sigbits;
    }
    __syncthreads();

    for (int t = tid; t < nv * 16; t += 1024) {
        int i = t >> 4, w = t & 15;
        u64 m = 0;
        int j0 = w << 6;
        int jend = min(j0 + 64, nv);
        int jstart = max(j0, i + 1);
        if (jstart < jend) {
            float xi1 = ox1[i], yi1 = oy1[i], xi2 = ox2[i], yi2 = oy2[i], ai = oar[i];
            for (int j = jstart; j < jend; j++) {
                float lx = fmaxf(xi1, ox1[j]), ly = fmaxf(yi1, oy1[j]);
                float rx = fminf(xi2, ox2[j]), ry = fminf(yi2, oy2[j]);
                float ww = rx - lx, hh = ry - ly;
                if (ww > 0.0f && hh > 0.0f) {
                    float inter = ww * hh;
                    float uni = ai + oar[j] - inter + 1e-9f;
                    if (__fdiv_rn(inter, uni) > 0.7f) m |= 1ULL << (j - j0);
                }
            }
        }
        mask[(i << 4) + w] = m;
    }
    __syncthreads();

    if (tid < 32) {
        u64 remv = 0;
        for (int i = 0; i < nv; i++) {
            unsigned sup = (unsigned)((remv >> (i & 63)) & 1ULL);
            sup = __shfl_sync(~0u, sup, i >> 6);
            if (tid == 0) keep[i] = sup ^ 1u;
            if (!sup && tid < 16) remv |= mask[(i << 4) + tid];
        }
    }
    __syncthreads();

    int kflag = (tid < nv) ? (int)keep[tid] : 0;
    int ktot;
    int kpos = bscan(kflag, misc + 8, tid, &ktot);
    if (kflag) {
        g_kb[b][l][kpos][0] = ux1[tid];
        g_kb[b][l][kpos][1] = uy1[tid];
        g_kb[b][l][kpos][2] = ux2[tid];
        g_kb[b][l][kpos][3] = uy2[tid];
        g_kkey[b][l][kpos] = ukeyv[tid];
    }
    if (tid == 0) g_kcnt[b][l] = ktot;
}

// ---- kernel 3: per-batch merge, sort by (sigmoid desc, lvl asc, rank asc) --
#define SMEM3 (FNPAD * 8 + 64)
__global__ __launch_bounds__(1024, 1)
void final_merge(float* __restrict__ out) {
    extern __shared__ unsigned char smraw[];
    u64* arr = (u64*)smraw;
    int* offs = (int*)(smraw + FNPAD * 8);
    int b = blockIdx.x, tid = threadIdx.x;
    if (tid == 0) {
        int s = 0;
        for (int l = 0; l < NLVL; l++) { offs[l] = s; s += g_kcnt[b][l]; }
        offs[NLVL] = s;
    }
    __syncthreads();
    int total = offs[NLVL];
    for (int t = tid; t < FNPAD; t += 1024) arr[t] = 0ULL;
    __syncthreads();
    for (int l = 0; l < NLVL; l++) {
        int c = g_kcnt[b][l], o = offs[l];
        for (int p = tid; p < c; p += 1024)
            arr[o + p] = ((u64)g_kkey[b][l][p] << 32)
                       | (unsigned)(0xFFFFFFFFu - (unsigned)((l << 16) | p));
    }
    __syncthreads();
    bitonic_desc(arr, FNPAD, tid);
    for (int j = tid; j < 1000; j += 1024) {
        float v0 = 0.f, v1 = 0.f, v2 = 0.f, v3 = 0.f;
        if (j < total) {
            unsigned tie = 0xFFFFFFFFu - (unsigned)(arr[j] & 0xFFFFFFFFu);
            int l = tie >> 16, p = tie & 0xFFFF;
            v0 = g_kb[b][l][p][0]; v1 = g_kb[b][l][p][1];
            v2 = g_kb[b][l][p][2]; v3 = g_kb[b][l][p][3];
        }
        ((float4*)out)[b * 1000 + j] = make_float4(v0, v1, v2, v3);
    }
}

static bool msz(const int* s, const int* ref) {
    for (int i = 0; i < 11; i++) if (s[i] != ref[i]) return false;
    return true;
}

extern "C" void kernel_launch(void* const* d_in, const int* in_sizes, int n_in,
                              void* d_out, int out_size) {
    const float *o[5], *dl[5], *anch;
    static const int inter[11] = {960000, 3840000, 240000, 960000, 60000,
                                  240000, 15000, 60000, 4056, 16224, 639528};
    static const int alpha[11] = {639528, 3840000, 960000, 240000, 60000,
                                  16224, 960000, 240000, 60000, 15000, 4056};
    if (n_in >= 11 && msz(in_sizes, inter)) {
        for (int i = 0; i < 5; i++) { o[i] = (const float*)d_in[2 * i]; dl[i] = (const float*)d_in[2 * i + 1]; }
        anch = (const float*)d_in[10];
    } else if (n_in >= 11 && msz(in_sizes, alpha)) {
        anch = (const float*)d_in[0];
        for (int i = 0; i < 5; i++) { dl[i] = (const float*)d_in[1 + i]; o[i] = (const float*)d_in[6 + i]; }
    } else {
        for (int i = 0; i < 5; i++) { o[i] = (const float*)d_in[i]; dl[i] = (const float*)d_in[5 + i]; }
        anch = (const float*)d_in[10];
    }
    (void)out_size;

    static int attr_done = 0;
    if (!attr_done) {
        cudaFuncSetAttribute(rpn_level_kernel, cudaFuncAttributeMaxDynamicSharedMemorySize, SMEM2);
        cudaFuncSetAttribute(final_merge, cudaFuncAttributeMaxDynamicSharedMemorySize, SMEM3);
        attr_done = 1;
    }

    permute_obj<<<(NBATCH * NTOT + 255) / 256, 256>>>(o[0], o[1], o[2], o[3], o[4]);
    rpn_level_kernel<<<NBATCH * NLVL, 1024, SMEM2>>>(dl[0], dl[1], dl[2], dl[3], dl[4], anch);
    final_merge<<<NBATCH, 1024, SMEM3>>>((float*)d_out);
}

// round 4
// speedup vs baseline: 4.7335x; 4.7335x over previous
#include <cuda_runtime.h>
#include <cstdint>

typedef unsigned long long u64;
typedef unsigned int u32;

#define NBATCH 8
#define NLVL 5
#define NBL 40
#define NPAD 1024
#define CAND 4096
#define FNPAD 8192
#define IMGSZ 800.0f
#define CLIPV 4.135166556742356f

__constant__ int c_h[NLVL]   = {200, 100, 50, 25, 13};
__constant__ int c_n[NLVL]   = {120000, 30000, 7500, 1875, 507};
__constant__ int c_off[NLVL] = {0, 120000, 150000, 157500, 159375};
__constant__ int c_k[NLVL]   = {1000, 1000, 1000, 1000, 507};

__device__ float4 g_obox[NBL][NPAD];   // offset coords (for IoU)
__device__ float  g_oar [NBL][NPAD];   // areas on offset coords
__device__ float4 g_ubox[NBL][NPAD];   // unoffset clipped coords (output)
__device__ u32    g_sig [NBL][NPAD];   // sigmoid bits (merge key)
__device__ int    g_nv  [NBL];
__device__ u64    g_mask[NBL][NPAD][16];
__device__ float4 g_kb  [NBL][NPAD];
__device__ u32    g_kkey[NBL][NPAD];
__device__ int    g_kcnt[NBL];

__device__ __forceinline__ u32 fkey(float f) {
    u32 u = __float_as_uint(f);
    return u ^ ((u32)((int)u >> 31) | 0x80000000u);
}
__device__ __forceinline__ float unfkey(u32 enc) {
    u32 u = (enc & 0x80000000u) ? (enc ^ 0x80000000u) : ~enc;
    return __uint_as_float(u);
}

__device__ __forceinline__ int bscan(int v, int* ws, int tid, int* total) {
    int lane = tid & 31, wid = tid >> 5;
    int x = v;
#pragma unroll
    for (int o = 1; o < 32; o <<= 1) {
        int y = __shfl_up_sync(~0u, x, o);
        if (lane >= o) x += y;
    }
    if (lane == 31) ws[wid] = x;
    __syncthreads();
    if (wid == 0) {
        int y = ws[lane];
#pragma unroll
        for (int o = 1; o < 32; o <<= 1) {
            int z = __shfl_up_sync(~0u, y, o);
            if (lane >= o) y += z;
        }
        ws[lane] = y;
    }
    __syncthreads();
    int base = wid ? ws[wid - 1] : 0;
    int tot = ws[31];
    __syncthreads();
    *total = tot;
    return base + x - v;
}

__device__ __forceinline__ void bitonic_desc(u64* a, int n, int tid) {
    for (int sz = 2; sz <= n; sz <<= 1)
        for (int st = sz >> 1; st >= 1; st >>= 1) {
            __syncthreads();
            for (int t = tid; t < (n >> 1); t += 1024) {
                int i = t + (t & ~(st - 1));
                int j = i + st;
                u64 x = a[i], y = a[j];
                if (((i & sz) == 0) ? (x < y) : (x > y)) { a[i] = y; a[j] = x; }
            }
        }
    __syncthreads();
}

// ---- K1: per (b,l): 2-scan exact top-k -> sort -> decode -> store cand ----
// smem: cand 32KB | hist 16KB | misc 1KB (256 ints)
#define SMEM1 (CAND * 8 + 4096 * 4 + 1024)

__global__ __launch_bounds__(1024, 1)
void k_select(const float* __restrict__ o0, const float* __restrict__ o1,
              const float* __restrict__ o2, const float* __restrict__ o3,
              const float* __restrict__ o4,
              const float* __restrict__ dl0, const float* __restrict__ dl1,
              const float* __restrict__ dl2, const float* __restrict__ dl3,
              const float* __restrict__ dl4, const float* __restrict__ anchors) {
    extern __shared__ unsigned char sm[];
    u64* cand = (u64*)sm;
    u32* hist = (u32*)(sm + CAND * 8);
    int* misc = (int*)(sm + CAND * 8 + 4096 * 4);   // 256 ints

    int tid = threadIdx.x;
    int bl = blockIdx.x, b = bl / NLVL, l = bl % NLVL;
    int h = c_h[l], n = c_n[l], kk = c_k[l], h2 = h * h;
    const float* ob = ((l == 0) ? o0 : (l == 1) ? o1 : (l == 2) ? o2 : (l == 3) ? o3 : o4)
                      + (size_t)b * 3 * h2;

    int m, S;
    if (l == 4) {
        for (int j = tid; j < NPAD; j += 1024) {
            u64 e = 0ULL;
            if (j < n) {
                int p = j / 3, a = j - p * 3, y = p / h, x = p - y * h;
                float v = ob[(a * h + y) * h + x];
                e = ((u64)fkey(v) << 32) | (u32)(~(u32)j);
            }
            cand[j] = e;
        }
        m = n; S = 1024;
        __syncthreads();
    } else {
        for (int q = tid; q < 4096; q += 1024) hist[q] = 0;
        __syncthreads();
        if (l < 3) {
            const float4* ob4 = (const float4*)ob;
            int n4 = n >> 2;
            for (int q = tid; q < n4; q += 1024) {
                float4 v = ob4[q];
                atomicAdd(&hist[fkey(v.x) >> 20], 1u);
                atomicAdd(&hist[fkey(v.y) >> 20], 1u);
                atomicAdd(&hist[fkey(v.z) >> 20], 1u);
                atomicAdd(&hist[fkey(v.w) >> 20], 1u);
            }
        } else {
            for (int q = tid; q < n; q += 1024)
                atomicAdd(&hist[fkey(ob[q]) >> 20], 1u);
        }
        __syncthreads();
        if (tid < 128) {                       // chunk sums: misc[8..135]
            u32 s = 0;
            for (int q = 0; q < 32; q++) s += hist[tid * 32 + q];
            misc[tid + 8] = (int)s;
        }
        __syncthreads();
        if (tid == 0) {
            int acc = 0, c;
            for (c = 127; c > 0; c--) {
                if (acc + misc[c + 8] >= kk) break;
                acc += misc[c + 8];
            }
            int bsel = c * 32;
            for (int q = 31; q >= 0; q--) {
                int hv = (int)hist[c * 32 + q];
                if (acc + hv >= kk) { bsel = c * 32 + q; break; }
                acc += hv;
            }
            misc[0] = 0; misc[1] = bsel;
        }
        __syncthreads();
        u32 B = (u32)misc[1];
        if (l < 3) {
            const float4* ob4 = (const float4*)ob;
            int n4 = n >> 2;
            for (int q = tid; q < n4; q += 1024) {
                float4 v = ob4[q];
                float vv[4] = {v.x, v.y, v.z, v.w};
#pragma unroll
                for (int e4 = 0; e4 < 4; e4++) {
                    u32 u = fkey(vv[e4]);
                    if ((u >> 20) >= B) {
                        int pos = atomicAdd(&misc[0], 1);
                        if (pos < CAND) {
                            int i0 = 4 * q + e4;
                            int a = (i0 >= h2) + (i0 >= 2 * h2);
                            int p = i0 - a * h2;
                            cand[pos] = ((u64)u << 32) | (u32)(~(u32)(p * 3 + a));
                        }
                    }
                }
            }
        } else {
            for (int q = tid; q < n; q += 1024) {
                u32 u = fkey(ob[q]);
                if ((u >> 20) >= B) {
                    int pos = atomicAdd(&misc[0], 1);
                    if (pos < CAND) {
                        int a = (q >= h2) + (q >= 2 * h2);
                        int p = q - a * h2;
                        cand[pos] = ((u64)u << 32) | (u32)(~(u32)(p * 3 + a));
                    }
                }
            }
        }
        __syncthreads();
        m = misc[0]; if (m > CAND) m = CAND;
        S = (m <= 1024) ? 1024 : ((m <= 2048) ? 2048 : 4096);
        for (int q = m + tid; q < S; q += 1024) cand[q] = 0ULL;
        __syncthreads();
    }

    bitonic_desc(cand, S, tid);   // (key desc, idx asc) == lax.top_k order

    float C = 4096.0f * (float)l;
    const float* dl = (l == 0) ? dl0 : (l == 1) ? dl1 : (l == 2) ? dl2 : (l == 3) ? dl3 : dl4;
    int valid = 0;
    float cx1 = 0.f, cy1 = 0.f, cx2 = 0.f, cy2 = 0.f;
    u32 sigbits = 0;
    if (tid < kk) {
        u64 e = cand[tid];
        u32 idx = ~(u32)(e & 0xFFFFFFFFu);
        float logit = unfkey((u32)(e >> 32));
        sigbits = __float_as_uint(__fdiv_rn(1.0f, 1.0f + expf(-logit)));
        int p = (int)(idx / 3u), a = (int)idx - p * 3;
        int y = p / h, x = p - y * h;
        int gi = c_off[l] + (int)idx;
        float ax1 = anchors[4 * gi], ay1 = anchors[4 * gi + 1];
        float ax2 = anchors[4 * gi + 2], ay2 = anchors[4 * gi + 3];
        float wa = ax2 - ax1, ha = ay2 - ay1;
        float cxa = ax1 + 0.5f * wa, cya = ay1 + 0.5f * ha;
        int dbase = ((b * 12 + a * 4) * h + y) * h + x;
        float dx = dl[dbase], dy = dl[dbase + h2];
        float dw = fminf(dl[dbase + 2 * h2], CLIPV);
        float dh = fminf(dl[dbase + 3 * h2], CLIPV);
        float cx = dx * wa + cxa, cy = dy * ha + cya;
        float pw = expf(dw) * wa, ph = expf(dh) * ha;
        cx1 = fminf(fmaxf(cx - 0.5f * pw, 0.0f), IMGSZ);
        cy1 = fminf(fmaxf(cy - 0.5f * ph, 0.0f), IMGSZ);
        cx2 = fminf(fmaxf(cx + 0.5f * pw, 0.0f), IMGSZ);
        cy2 = fminf(fmaxf(cy + 0.5f * ph, 0.0f), IMGSZ);
        valid = ((cx2 - cx1) >= 1e-3f && (cy2 - cy1) >= 1e-3f) ? 1 : 0;
    }
    __syncthreads();

    int nv;
    int vpos = bscan(valid, misc + 144, tid, &nv);   // ws: misc[144..175]
    if (valid) {
        float xo1 = cx1 + C, yo1 = cy1 + C, xo2 = cx2 + C, yo2 = cy2 + C;
        g_obox[bl][vpos] = make_float4(xo1, yo1, xo2, yo2);
        g_oar[bl][vpos] = (xo2 - xo1) * (yo2 - yo1);
        g_ubox[bl][vpos] = make_float4(cx1, cy1, cx2, cy2);
        g_sig[bl][vpos] = sigbits;
    }
    if (tid == 0) g_nv[bl] = nv;
}

// ---- K2: mask builder, full-chip parallel: grid (40, 16) x 256 -----------
__global__ void k_mask() {
    int bl = blockIdx.x, w = blockIdx.y;
    int nv = g_nv[bl];
    int j0 = w << 6;
    if (j0 >= nv) return;   // words beyond nv never read by k_nms
    __shared__ float4 jb[64];
    __shared__ float  ja[64];
    int tid = threadIdx.x;
    int jend = min(j0 + 64, nv);
    if (tid < jend - j0) { jb[tid] = g_obox[bl][j0 + tid]; ja[tid] = g_oar[bl][j0 + tid]; }
    __syncthreads();
    for (int i = tid; i < nv; i += 256) {
        u64 mword = 0;
        int js = max(j0, i + 1) - j0, je = jend - j0;
        if (js < je) {
            float4 bi = g_obox[bl][i];
            float ai = g_oar[bl][i];
            for (int jj = js; jj < je; jj++) {
                float4 bj = jb[jj];
                float lx = fmaxf(bi.x, bj.x), ly = fmaxf(bi.y, bj.y);
                float rx = fminf(bi.z, bj.z), ry = fminf(bi.w, bj.w);
                float ww2 = rx - lx, hh2 = ry - ly;
                if (ww2 > 0.0f && hh2 > 0.0f) {
                    float inter = ww2 * hh2;
                    float uni = ai + ja[jj] - inter + 1e-9f;
                    if (__fdiv_rn(inter, uni) > 0.7f) mword |= 1ULL << jj;
                }
            }
        }
        g_mask[bl][i][w] = mword;
    }
}

// ---- K3: fixed-point greedy NMS (unique fixed point == greedy) + compact --
#define SMEM3K (131072 + 512)
__global__ __launch_bounds__(1024, 1)
void k_nms() {
    extern __shared__ unsigned char sm[];
    u64* smask = (u64*)sm;                 // up to 128KB
    u64* cur   = (u64*)(sm + 131072);      // 16
    u64* nxt   = cur + 16;
    int* misc  = (int*)(nxt + 16);         // flag + scan ws (36 ints < 256B)
    int tid = threadIdx.x, bl = blockIdx.x;
    int nv = g_nv[bl];
    const u64* gm = &g_mask[bl][0][0];
    for (int t = tid; t < nv * 16; t += 1024) smask[t] = gm[t];
    if (tid < 16) cur[tid] = 0ULL;
    __syncthreads();

    int w = tid & 15, i0 = tid >> 4;
    for (int it = 0; it < NPAD; it++) {
        if (tid < 16) nxt[tid] = 0ULL;
        if (tid == 0) misc[0] = 0;
        __syncthreads();
        u64 acc = 0;
        for (int i = i0; i < nv; i += 64)
            if (!((cur[i >> 6] >> (i & 63)) & 1ULL)) acc |= smask[i * 16 + w];
        if (acc) atomicOr(&nxt[w], acc);
        __syncthreads();
        if (tid < 16) {
            if (nxt[tid] != cur[tid]) misc[0] = 1;
            cur[tid] = nxt[tid];
        }
        __syncthreads();
        if (!misc[0]) break;
    }

    int keepf = (tid < nv) && !((cur[tid >> 6] >> (tid & 63)) & 1ULL);
    int ktot;
    int kpos = bscan(keepf, misc + 4, tid, &ktot);
    if (keepf) {
        g_kb[bl][kpos] = g_ubox[bl][tid];
        g_kkey[bl][kpos] = g_sig[bl][tid];
    }
    if (tid == 0) g_kcnt[bl] = ktot;
}

// ---- K4: per-batch merge, sort by (sigmoid desc, lvl asc, rank asc) ------
#define SMEM4K (FNPAD * 8 + 64)
__global__ __launch_bounds__(1024, 1)
void k_merge(float* __restrict__ out) {
    extern __shared__ unsigned char sm[];
    u64* arr = (u64*)sm;
    int* offs = (int*)(sm + FNPAD * 8);
    int b = blockIdx.x, tid = threadIdx.x;
    if (tid == 0) {
        int s = 0;
        for (int l = 0; l < NLVL; l++) { offs[l] = s; s += g_kcnt[b * NLVL + l]; }
        offs[NLVL] = s;
    }
    __syncthreads();
    int total = offs[NLVL];
    int S = (total <= 2048) ? 2048 : ((total <= 4096) ? 4096 : FNPAD);
    for (int t = tid; t < S; t += 1024) arr[t] = 0ULL;
    __syncthreads();
    for (int l = 0; l < NLVL; l++) {
        int c = g_kcnt[b * NLVL + l], o = offs[l];
        for (int p = tid; p < c; p += 1024)
            arr[o + p] = ((u64)g_kkey[b * NLVL + l][p] << 32)
                       | (u32)(0xFFFFFFFFu - (u32)((l << 16) | p));
    }
    __syncthreads();
    bitonic_desc(arr, S, tid);
    for (int j = tid; j < 1000; j += 1024) {
        float v0 = 0.f, v1 = 0.f, v2 = 0.f, v3 = 0.f;
        if (j < total) {
            u32 tie = 0xFFFFFFFFu - (u32)(arr[j] & 0xFFFFFFFFu);
            int l = tie >> 16, p = tie & 0xFFFF;
            float4 bx = g_kb[b * NLVL + l][p];
            v0 = bx.x; v1 = bx.y; v2 = bx.z; v3 = bx.w;
        }
        ((float4*)out)[b * 1000 + j] = make_float4(v0, v1, v2, v3);
    }
}

static bool msz(const int* s, const int* ref) {
    for (int i = 0; i < 11; i++) if (s[i] != ref[i]) return false;
    return true;
}

extern "C" void kernel_launch(void* const* d_in, const int* in_sizes, int n_in,
                              void* d_out, int out_size) {
    const float *o[5], *dl[5], *anch;
    static const int inter[11] = {960000, 3840000, 240000, 960000, 60000,
                                  240000, 15000, 60000, 4056, 16224, 639528};
    static const int alpha[11] = {639528, 3840000, 960000, 240000, 60000,
                                  16224, 960000, 240000, 60000, 15000, 4056};
    if (n_in >= 11 && msz(in_sizes, inter)) {
        for (int i = 0; i < 5; i++) { o[i] = (const float*)d_in[2 * i]; dl[i] = (const float*)d_in[2 * i + 1]; }
        anch = (const float*)d_in[10];
    } else if (n_in >= 11 && msz(in_sizes, alpha)) {
        anch = (const float*)d_in[0];
        for (int i = 0; i < 5; i++) { dl[i] = (const float*)d_in[1 + i]; o[i] = (const float*)d_in[6 + i]; }
    } else {
        for (int i = 0; i < 5; i++) { o[i] = (const float*)d_in[i]; dl[i] = (const float*)d_in[5 + i]; }
        anch = (const float*)d_in[10];
    }
    (void)out_size;

    static int attr_done = 0;
    if (!attr_done) {
        cudaFuncSetAttribute(k_select, cudaFuncAttributeMaxDynamicSharedMemorySize, SMEM1);
        cudaFuncSetAttribute(k_nms, cudaFuncAttributeMaxDynamicSharedMemorySize, SMEM3K);
        cudaFuncSetAttribute(k_merge, cudaFuncAttributeMaxDynamicSharedMemorySize, SMEM4K);
        attr_done = 1;
    }

    k_select<<<NBL, 1024, SMEM1>>>(o[0], o[1], o[2], o[3], o[4],
                                   dl[0], dl[1], dl[2], dl[3], dl[4], anch);
    k_mask<<<dim3(NBL, 16), 256>>>();
    k_nms<<<NBL, 1024, SMEM3K>>>();
    k_merge<<<NBATCH, 1024, SMEM4K>>>((float*)d_out);
}

// round 5
// speedup vs baseline: 5.6032x; 1.1837x over previous
#include <cuda_runtime.h>
#include <cstdint>

typedef unsigned long long u64;
typedef unsigned int u32;

#define NBATCH 8
#define NLVL 5
#define NBL 40
#define NPAD 1024
#define CAND 4096
#define IMGSZ 800.0f
#define CLIPV 4.135166556742356f

__constant__ int c_h[NLVL]   = {200, 100, 50, 25, 13};
__constant__ int c_n[NLVL]   = {120000, 30000, 7500, 1875, 507};
__constant__ int c_off[NLVL] = {0, 120000, 150000, 157500, 159375};
__constant__ int c_k[NLVL]   = {1000, 1000, 1000, 1000, 507};

__device__ float4 g_obox[NBL][NPAD];   // offset coords (for IoU)
__device__ float  g_oar [NBL][NPAD];   // areas on offset coords
__device__ float4 g_ubox[NBL][NPAD];   // unoffset clipped coords (output)
__device__ u32    g_sig [NBL][NPAD];   // sigmoid bits (merge key)
__device__ int    g_nv  [NBL];
__device__ u64    g_mask[NBL][NPAD][16];
__device__ float4 g_kb  [NBL][NPAD];
__device__ u32    g_kkey[NBL][NPAD];
__device__ int    g_kcnt[NBL];

__device__ __forceinline__ u32 fkey(float f) {
    u32 u = __float_as_uint(f);
    return u ^ ((u32)((int)u >> 31) | 0x80000000u);
}
__device__ __forceinline__ float unfkey(u32 enc) {
    u32 u = (enc & 0x80000000u) ? (enc ^ 0x80000000u) : ~enc;
    return __uint_as_float(u);
}

__device__ __forceinline__ int bscan(int v, int* ws, int tid, int* total) {
    int lane = tid & 31, wid = tid >> 5;
    int x = v;
#pragma unroll
    for (int o = 1; o < 32; o <<= 1) {
        int y = __shfl_up_sync(~0u, x, o);
        if (lane >= o) x += y;
    }
    if (lane == 31) ws[wid] = x;
    __syncthreads();
    if (wid == 0) {
        int y = ws[lane];
#pragma unroll
        for (int o = 1; o < 32; o <<= 1) {
            int z = __shfl_up_sync(~0u, y, o);
            if (lane >= o) y += z;
        }
        ws[lane] = y;
    }
    __syncthreads();
    int base = wid ? ws[wid - 1] : 0;
    int tot = ws[31];
    __syncthreads();
    *total = tot;
    return base + x - v;
}

__device__ __forceinline__ void bitonic_desc(u64* a, int n, int tid) {
    for (int sz = 2; sz <= n; sz <<= 1)
        for (int st = sz >> 1; st >= 1; st >>= 1) {
            __syncthreads();
            for (int t = tid; t < (n >> 1); t += 1024) {
                int i = t + (t & ~(st - 1));
                int j = i + st;
                u64 x = a[i], y = a[j];
                if (((i & sz) == 0) ? (x < y) : (x > y)) { a[i] = y; a[j] = x; }
            }
        }
    __syncthreads();
}

// ---- K1: per (b,l): 2-scan exact top-k -> sort -> decode -> store cand ----
// smem: cand 32KB | hist 16KB | misc 1KB (256 ints)
#define SMEM1 (CAND * 8 + 4096 * 4 + 1024)

__global__ __launch_bounds__(1024, 1)
void k_select(const float* __restrict__ o0, const float* __restrict__ o1,
              const float* __restrict__ o2, const float* __restrict__ o3,
              const float* __restrict__ o4,
              const float* __restrict__ dl0, const float* __restrict__ dl1,
              const float* __restrict__ dl2, const float* __restrict__ dl3,
              const float* __restrict__ dl4, const float* __restrict__ anchors) {
    extern __shared__ unsigned char sm[];
    u64* cand = (u64*)sm;
    u32* hist = (u32*)(sm + CAND * 8);
    int* misc = (int*)(sm + CAND * 8 + 4096 * 4);   // 256 ints

    int tid = threadIdx.x;
    int bl = blockIdx.x, b = bl / NLVL, l = bl % NLVL;
    int h = c_h[l], n = c_n[l], kk = c_k[l], h2 = h * h;
    const float* ob = ((l == 0) ? o0 : (l == 1) ? o1 : (l == 2) ? o2 : (l == 3) ? o3 : o4)
                      + (size_t)b * 3 * h2;

    int m, S;
    if (l == 4) {
        for (int j = tid; j < NPAD; j += 1024) {
            u64 e = 0ULL;
            if (j < n) {
                int p = j / 3, a = j - p * 3, y = p / h, x = p - y * h;
                float v = ob[(a * h + y) * h + x];
                e = ((u64)fkey(v) << 32) | (u32)(~(u32)j);
            }
            cand[j] = e;
        }
        m = n; S = 1024;
        __syncthreads();
    } else {
        for (int q = tid; q < 4096; q += 1024) hist[q] = 0;
        __syncthreads();
        if (l < 3) {
            const float4* ob4 = (const float4*)ob;
            int n4 = n >> 2;
            for (int q = tid; q < n4; q += 1024) {
                float4 v = ob4[q];
                atomicAdd(&hist[fkey(v.x) >> 20], 1u);
                atomicAdd(&hist[fkey(v.y) >> 20], 1u);
                atomicAdd(&hist[fkey(v.z) >> 20], 1u);
                atomicAdd(&hist[fkey(v.w) >> 20], 1u);
            }
        } else {
            for (int q = tid; q < n; q += 1024)
                atomicAdd(&hist[fkey(ob[q]) >> 20], 1u);
        }
        __syncthreads();
        if (tid < 128) {                       // chunk sums: misc[8..135]
            u32 s = 0;
            for (int q = 0; q < 32; q++) s += hist[tid * 32 + q];
            misc[tid + 8] = (int)s;
        }
        __syncthreads();
        if (tid == 0) {
            int acc = 0, c;
            for (c = 127; c > 0; c--) {
                if (acc + misc[c + 8] >= kk) break;
                acc += misc[c + 8];
            }
            int bsel = c * 32;
            for (int q = 31; q >= 0; q--) {
                int hv = (int)hist[c * 32 + q];
                if (acc + hv >= kk) { bsel = c * 32 + q; break; }
                acc += hv;
            }
            misc[0] = 0; misc[1] = bsel;
        }
        __syncthreads();
        u32 B = (u32)misc[1];
        if (l < 3) {
            const float4* ob4 = (const float4*)ob;
            int n4 = n >> 2;
            for (int q = tid; q < n4; q += 1024) {
                float4 v = ob4[q];
                float vv[4] = {v.x, v.y, v.z, v.w};
#pragma unroll
                for (int e4 = 0; e4 < 4; e4++) {
                    u32 u = fkey(vv[e4]);
                    if ((u >> 20) >= B) {
                        int pos = atomicAdd(&misc[0], 1);
                        if (pos < CAND) {
                            int i0 = 4 * q + e4;
                            int a = (i0 >= h2) + (i0 >= 2 * h2);
                            int p = i0 - a * h2;
                            cand[pos] = ((u64)u << 32) | (u32)(~(u32)(p * 3 + a));
                        }
                    }
                }
            }
        } else {
            for (int q = tid; q < n; q += 1024) {
                u32 u = fkey(ob[q]);
                if ((u >> 20) >= B) {
                    int pos = atomicAdd(&misc[0], 1);
                    if (pos < CAND) {
                        int a = (q >= h2) + (q >= 2 * h2);
                        int p = q - a * h2;
                        cand[pos] = ((u64)u << 32) | (u32)(~(u32)(p * 3 + a));
                    }
                }
            }
        }
        __syncthreads();
        m = misc[0]; if (m > CAND) m = CAND;
        S = (m <= 1024) ? 1024 : ((m <= 2048) ? 2048 : 4096);
        for (int q = m + tid; q < S; q += 1024) cand[q] = 0ULL;
        __syncthreads();
    }

    bitonic_desc(cand, S, tid);   // (key desc, idx asc) == lax.top_k order

    float C = 4096.0f * (float)l;
    const float* dl = (l == 0) ? dl0 : (l == 1) ? dl1 : (l == 2) ? dl2 : (l == 3) ? dl3 : dl4;
    int valid = 0;
    float cx1 = 0.f, cy1 = 0.f, cx2 = 0.f, cy2 = 0.f;
    u32 sigbits = 0;
    if (tid < kk) {
        u64 e = cand[tid];
        u32 idx = ~(u32)(e & 0xFFFFFFFFu);
        float logit = unfkey((u32)(e >> 32));
        sigbits = __float_as_uint(__fdiv_rn(1.0f, 1.0f + expf(-logit)));
        int p = (int)(idx / 3u), a = (int)idx - p * 3;
        int y = p / h, x = p - y * h;
        int gi = c_off[l] + (int)idx;
        float ax1 = anchors[4 * gi], ay1 = anchors[4 * gi + 1];
        float ax2 = anchors[4 * gi + 2], ay2 = anchors[4 * gi + 3];
        float wa = ax2 - ax1, ha = ay2 - ay1;
        float cxa = ax1 + 0.5f * wa, cya = ay1 + 0.5f * ha;
        int dbase = ((b * 12 + a * 4) * h + y) * h + x;
        float dx = dl[dbase], dy = dl[dbase + h2];
        float dw = fminf(dl[dbase + 2 * h2], CLIPV);
        float dh = fminf(dl[dbase + 3 * h2], CLIPV);
        float cx = dx * wa + cxa, cy = dy * ha + cya;
        float pw = expf(dw) * wa, ph = expf(dh) * ha;
        cx1 = fminf(fmaxf(cx - 0.5f * pw, 0.0f), IMGSZ);
        cy1 = fminf(fmaxf(cy - 0.5f * ph, 0.0f), IMGSZ);
        cx2 = fminf(fmaxf(cx + 0.5f * pw, 0.0f), IMGSZ);
        cy2 = fminf(fmaxf(cy + 0.5f * ph, 0.0f), IMGSZ);
        valid = ((cx2 - cx1) >= 1e-3f && (cy2 - cy1) >= 1e-3f) ? 1 : 0;
    }
    __syncthreads();

    int nv;
    int vpos = bscan(valid, misc + 144, tid, &nv);   // ws: misc[144..175]
    if (valid) {
        float xo1 = cx1 + C, yo1 = cy1 + C, xo2 = cx2 + C, yo2 = cy2 + C;
        g_obox[bl][vpos] = make_float4(xo1, yo1, xo2, yo2);
        g_oar[bl][vpos] = (xo2 - xo1) * (yo2 - yo1);
        g_ubox[bl][vpos] = make_float4(cx1, cy1, cx2, cy2);
        g_sig[bl][vpos] = sigbits;
    }
    if (tid == 0) g_nv[bl] = nv;
}

// ---- K2: mask builder, full-chip parallel: grid (40, 16) x 256 -----------
__global__ void k_mask() {
    int bl = blockIdx.x, w = blockIdx.y;
    int nv = g_nv[bl];
    int j0 = w << 6;
    if (j0 >= nv) return;   // words beyond nv never read by k_nms
    __shared__ float4 jb[64];
    __shared__ float  ja[64];
    int tid = threadIdx.x;
    int jend = min(j0 + 64, nv);
    if (tid < jend - j0) { jb[tid] = g_obox[bl][j0 + tid]; ja[tid] = g_oar[bl][j0 + tid]; }
    __syncthreads();
    for (int i = tid; i < nv; i += 256) {
        u64 mword = 0;
        int js = max(j0, i + 1) - j0, je = jend - j0;
        if (js < je) {
            float4 bi = g_obox[bl][i];
            float ai = g_oar[bl][i];
            for (int jj = js; jj < je; jj++) {
                float4 bj = jb[jj];
                float lx = fmaxf(bi.x, bj.x), ly = fmaxf(bi.y, bj.y);
                float rx = fminf(bi.z, bj.z), ry = fminf(bi.w, bj.w);
                float ww2 = rx - lx, hh2 = ry - ly;
                if (ww2 > 0.0f && hh2 > 0.0f) {
                    float inter = ww2 * hh2;
                    float uni = ai + ja[jj] - inter + 1e-9f;
                    if (__fdiv_rn(inter, uni) > 0.7f) mword |= 1ULL << jj;
                }
            }
        }
        g_mask[bl][i][w] = mword;
    }
}

// ---- K3: fixed-point greedy NMS (unique fixed point == greedy) + compact --
#define SMEM3K (131072 + 512)
__global__ __launch_bounds__(1024, 1)
void k_nms() {
    extern __shared__ unsigned char sm[];
    u64* smask = (u64*)sm;                 // up to 128KB
    u64* cur   = (u64*)(sm + 131072);      // 16
    u64* nxt   = cur + 16;
    int* misc  = (int*)(nxt + 16);
    int tid = threadIdx.x, bl = blockIdx.x;
    int nv = g_nv[bl];
    const u64* gm = &g_mask[bl][0][0];
    for (int t = tid; t < nv * 16; t += 1024) smask[t] = gm[t];
    if (tid < 16) cur[tid] = 0ULL;
    __syncthreads();

    int w = tid & 15, i0 = tid >> 4;
    for (int it = 0; it < NPAD; it++) {
        if (tid < 16) nxt[tid] = 0ULL;
        if (tid == 0) misc[0] = 0;
        __syncthreads();
        u64 acc = 0;
        for (int i = i0; i < nv; i += 64)
            if (!((cur[i >> 6] >> (i & 63)) & 1ULL)) acc |= smask[i * 16 + w];
        if (acc) atomicOr(&nxt[w], acc);
        __syncthreads();
        if (tid < 16) {
            if (nxt[tid] != cur[tid]) misc[0] = 1;
            cur[tid] = nxt[tid];
        }
        __syncthreads();
        if (!misc[0]) break;
    }

    int keepf = (tid < nv) && !((cur[tid >> 6] >> (tid & 63)) & 1ULL);
    int ktot;
    int kpos = bscan(keepf, misc + 4, tid, &ktot);
    if (keepf) {
        g_kb[bl][kpos] = g_ubox[bl][tid];
        g_kkey[bl][kpos] = g_sig[bl][tid];
    }
    if (tid == 0) g_kcnt[bl] = ktot;
}

// ---- K4: sortless 5-way merge by rank computation ------------------------
// Per-level kept lists are already sorted (key desc, rank asc). Global rank of
// element (l,p,key s) under the reference order (key desc, lvl asc, rank asc):
//   rank = p + sum_{l'<l} #{key' >= s} + sum_{l'>l} #{key' > s}
// Ranks are a permutation -> direct scatter, no sort, 3 barriers total.
__global__ __launch_bounds__(1024, 1)
void k_merge(float* __restrict__ out) {
    __shared__ u32 skeys[NLVL][NPAD];
    __shared__ int cnt[NLVL], off[NLVL + 1];
    int b = blockIdx.x, tid = threadIdx.x;
    if (tid < NLVL) cnt[tid] = g_kcnt[b * NLVL + tid];
    __syncthreads();
    if (tid == 0) {
        int s = 0;
        for (int l = 0; l < NLVL; l++) { off[l] = s; s += cnt[l]; }
        off[NLVL] = s;
    }
    __syncthreads();
    int total = off[NLVL];
    for (int l = 0; l < NLVL; l++)
        for (int p = tid; p < cnt[l]; p += 1024)
            skeys[l][p] = g_kkey[b * NLVL + l][p];
    __syncthreads();

    // zero-fill rows with no element (output poisoned to 0xAA)
    for (int j = total + tid; j < 1000; j += 1024)
        ((float4*)out)[b * 1000 + j] = make_float4(0.f, 0.f, 0.f, 0.f);

    for (int e = tid; e < total; e += 1024) {
        int l = 0;
        while (l < NLVL - 1 && e >= off[l + 1]) l++;
        int p = e - off[l];
        u32 s = skeys[l][p];
        int rank = p;
#pragma unroll
        for (int l2 = 0; l2 < NLVL; l2++) {
            if (l2 == l) continue;
            const u32* a = skeys[l2];
            int lo = 0, hi = cnt[l2];
            if (l2 < l) {           // count keys >= s: first idx with a[idx] < s
                while (lo < hi) { int mid = (lo + hi) >> 1; if (a[mid] < s) hi = mid; else lo = mid + 1; }
            } else {                // count keys >  s: first idx with a[idx] <= s
                while (lo < hi) { int mid = (lo + hi) >> 1; if (a[mid] <= s) hi = mid; else lo = mid + 1; }
            }
            rank += lo;
        }
        if (rank < 1000)
            ((float4*)out)[b * 1000 + rank] = g_kb[b * NLVL + l][p];
    }
}

static bool msz(const int* s, const int* ref) {
    for (int i = 0; i < 11; i++) if (s[i] != ref[i]) return false;
    return true;
}

extern "C" void kernel_launch(void* const* d_in, const int* in_sizes, int n_in,
                              void* d_out, int out_size) {
    const float *o[5], *dl[5], *anch;
    static const int inter[11] = {960000, 3840000, 240000, 960000, 60000,
                                  240000, 15000, 60000, 4056, 16224, 639528};
    static const int alpha[11] = {639528, 3840000, 960000, 240000, 60000,
                                  16224, 960000, 240000, 60000, 15000, 4056};
    if (n_in >= 11 && msz(in_sizes, inter)) {
        for (int i = 0; i < 5; i++) { o[i] = (const float*)d_in[2 * i]; dl[i] = (const float*)d_in[2 * i + 1]; }
        anch = (const float*)d_in[10];
    } else if (n_in >= 11 && msz(in_sizes, alpha)) {
        anch = (const float*)d_in[0];
        for (int i = 0; i < 5; i++) { dl[i] = (const float*)d_in[1 + i]; o[i] = (const float*)d_in[6 + i]; }
    } else {
        for (int i = 0; i < 5; i++) { o[i] = (const float*)d_in[i]; dl[i] = (const float*)d_in[5 + i]; }
        anch = (const float*)d_in[10];
    }
    (void)out_size;

    static int attr_done = 0;
    if (!attr_done) {
        cudaFuncSetAttribute(k_select, cudaFuncAttributeMaxDynamicSharedMemorySize, SMEM1);
        cudaFuncSetAttribute(k_nms, cudaFuncAttributeMaxDynamicSharedMemorySize, SMEM3K);
        attr_done = 1;
    }

    k_select<<<NBL, 1024, SMEM1>>>(o[0], o[1], o[2], o[3], o[4],
                                   dl[0], dl[1], dl[2], dl[3], dl[4], anch);
    k_mask<<<dim3(NBL, 16), 256>>>();
    k_nms<<<NBL, 1024, SMEM3K>>>();
    k_merge<<<NBATCH, 1024>>>((float*)d_out);
}

// round 6
// speedup vs baseline: 5.6999x; 1.0173x over previous
#include <cuda_runtime.h>
#include <cstdint>

typedef unsigned long long u64;
typedef unsigned int u32;

#define NBATCH 8
#define NLVL 5
#define NBL 40
#define NCH 16
#define NPAD 1024
#define CAND 4096
#define IMGSZ 800.0f
#define CLIPV 4.135166556742356f

__constant__ int c_h[NLVL]   = {200, 100, 50, 25, 13};
__constant__ int c_n[NLVL]   = {120000, 30000, 7500, 1875, 507};
__constant__ int c_off[NLVL] = {0, 120000, 150000, 157500, 159375};
__constant__ int c_k[NLVL]   = {1000, 1000, 1000, 1000, 507};

__device__ u32    g_hist16[NBL][NCH][4096];
__device__ u32    g_B[NBL];
__device__ int    g_ccnt[NBL];
__device__ u64    g_cand[NBL][CAND];
__device__ float4 g_obox[NBL][NPAD];
__device__ float  g_oar [NBL][NPAD];
__device__ float4 g_ubox[NBL][NPAD];
__device__ u32    g_sig [NBL][NPAD];
__device__ int    g_nv  [NBL];
__device__ u64    g_mask[NBL][NPAD][16];
__device__ float4 g_kb  [NBL][NPAD];
__device__ u32    g_kkey[NBL][NPAD];
__device__ int    g_kcnt[NBL];

__device__ __forceinline__ u32 fkey(float f) {
    u32 u = __float_as_uint(f);
    return u ^ ((u32)((int)u >> 31) | 0x80000000u);
}
__device__ __forceinline__ float unfkey(u32 enc) {
    u32 u = (enc & 0x80000000u) ? (enc ^ 0x80000000u) : ~enc;
    return __uint_as_float(u);
}

__device__ __forceinline__ int bscan(int v, int* ws, int tid, int* total) {
    int lane = tid & 31, wid = tid >> 5;
    int x = v;
#pragma unroll
    for (int o = 1; o < 32; o <<= 1) {
        int y = __shfl_up_sync(~0u, x, o);
        if (lane >= o) x += y;
    }
    if (lane == 31) ws[wid] = x;
    __syncthreads();
    if (wid == 0) {
        int y = ws[lane];
#pragma unroll
        for (int o = 1; o < 32; o <<= 1) {
            int z = __shfl_up_sync(~0u, y, o);
            if (lane >= o) y += z;
        }
        ws[lane] = y;
    }
    __syncthreads();
    int base = wid ? ws[wid - 1] : 0;
    int tot = ws[31];
    __syncthreads();
    *total = tot;
    return base + x - v;
}

__device__ __forceinline__ void bitonic_desc(u64* a, int n, int tid) {
    for (int sz = 2; sz <= n; sz <<= 1)
        for (int st = sz >> 1; st >= 1; st >>= 1) {
            __syncthreads();
            for (int t = tid; t < (n >> 1); t += 1024) {
                int i = t + (t & ~(st - 1));
                int j = i + st;
                u64 x = a[i], y = a[j];
                if (((i & sz) == 0) ? (x < y) : (x > y)) { a[i] = y; a[j] = x; }
            }
        }
    __syncthreads();
}

// ---- K0: per-chunk private histograms (no atomics to global, no zeroing) --
__global__ void k_hist(const float* __restrict__ o0, const float* __restrict__ o1,
                       const float* __restrict__ o2, const float* __restrict__ o3) {
    int bl = blockIdx.x, c = blockIdx.y, tid = threadIdx.x;
    int b = bl / NLVL, l = bl % NLVL;
    if (l == 4) return;
    int h2 = c_h[l] * c_h[l], n = c_n[l];
    const float* ob = ((l == 0) ? o0 : (l == 1) ? o1 : (l == 2) ? o2 : o3) + (size_t)b * 3 * h2;
    __shared__ u32 hist[4096];
    for (int q = tid; q < 4096; q += 256) hist[q] = 0;
    __syncthreads();
    if (l < 3) {
        const float4* ob4 = (const float4*)ob;
        int n4 = n >> 2, cs = (n4 + NCH - 1) / NCH;
        int qs = c * cs, qe = min(qs + cs, n4);
        for (int q = qs + tid; q < qe; q += 256) {
            float4 v = ob4[q];
            atomicAdd(&hist[fkey(v.x) >> 20], 1u);
            atomicAdd(&hist[fkey(v.y) >> 20], 1u);
            atomicAdd(&hist[fkey(v.z) >> 20], 1u);
            atomicAdd(&hist[fkey(v.w) >> 20], 1u);
        }
    } else {
        int cs = (n + NCH - 1) / NCH;
        int qs = c * cs, qe = min(qs + cs, n);
        for (int q = qs + tid; q < qe; q += 256)
            atomicAdd(&hist[fkey(ob[q]) >> 20], 1u);
    }
    __syncthreads();
    for (int q = tid; q < 4096; q += 256) g_hist16[bl][c][q] = hist[q];
}

// ---- K1: reduce hists, pick threshold bucket, reset counters --------------
__global__ __launch_bounds__(1024, 1) void k_thresh() {
    int bl = blockIdx.x, l = bl % NLVL, tid = threadIdx.x;
    if (l == 4) return;
    __shared__ u32 hist[4096];
    __shared__ int misc[160];
    for (int j = tid; j < 4096; j += 1024) {
        u32 s = 0;
#pragma unroll
        for (int c = 0; c < NCH; c++) s += g_hist16[bl][c][j];
        hist[j] = s;
    }
    __syncthreads();
    if (tid < 128) {
        u32 s = 0;
        for (int q = 0; q < 32; q++) s += hist[tid * 32 + q];
        misc[tid + 8] = (int)s;
    }
    __syncthreads();
    if (tid == 0) {
        int kk = c_k[l];
        int acc = 0, c;
        for (c = 127; c > 0; c--) {
            if (acc + misc[c + 8] >= kk) break;
            acc += misc[c + 8];
        }
        int bsel = c * 32;
        for (int q = 31; q >= 0; q--) {
            int hv = (int)hist[c * 32 + q];
            if (acc + hv >= kk) { bsel = c * 32 + q; break; }
            acc += hv;
        }
        g_B[bl] = (u32)bsel;
        g_ccnt[bl] = 0;
    }
}

// ---- K2: compact candidates >= threshold bucket (order fixed by sort) -----
__global__ void k_compact(const float* __restrict__ o0, const float* __restrict__ o1,
                          const float* __restrict__ o2, const float* __restrict__ o3) {
    int bl = blockIdx.x, c = blockIdx.y, tid = threadIdx.x;
    int b = bl / NLVL, l = bl % NLVL;
    if (l == 4) return;
    int h2 = c_h[l] * c_h[l], n = c_n[l];
    const float* ob = ((l == 0) ? o0 : (l == 1) ? o1 : (l == 2) ? o2 : o3) + (size_t)b * 3 * h2;
    u32 B = g_B[bl];
    if (l < 3) {
        const float4* ob4 = (const float4*)ob;
        int n4 = n >> 2, cs = (n4 + NCH - 1) / NCH;
        int qs = c * cs, qe = min(qs + cs, n4);
        for (int q = qs + tid; q < qe; q += 256) {
            float4 v = ob4[q];
            float vv[4] = {v.x, v.y, v.z, v.w};
#pragma unroll
            for (int e4 = 0; e4 < 4; e4++) {
                u32 u = fkey(vv[e4]);
                if ((u >> 20) >= B) {
                    int pos = atomicAdd(&g_ccnt[bl], 1);
                    if (pos < CAND) {
                        int i0 = 4 * q + e4;
                        int a = (i0 >= h2) + (i0 >= 2 * h2);
                        int p = i0 - a * h2;
                        g_cand[bl][pos] = ((u64)u << 32) | (u32)(~(u32)(p * 3 + a));
                    }
                }
            }
        }
    } else {
        int cs = (n + NCH - 1) / NCH;
        int qs = c * cs, qe = min(qs + cs, n);
        for (int q = qs + tid; q < qe; q += 256) {
            u32 u = fkey(ob[q]);
            if ((u >> 20) >= B) {
                int pos = atomicAdd(&g_ccnt[bl], 1);
                if (pos < CAND) {
                    int a = (q >= h2) + (q >= 2 * h2);
                    int p = q - a * h2;
                    g_cand[bl][pos] = ((u64)u << 32) | (u32)(~(u32)(p * 3 + a));
                }
            }
        }
    }
}

// ---- K3: per (b,l): sort candidates -> decode -> validity compact ---------
#define SMEM3 (CAND * 8 + 1024)
__global__ __launch_bounds__(1024, 1)
void k_sortdecode(const float* __restrict__ o4,
                  const float* __restrict__ dl0, const float* __restrict__ dl1,
                  const float* __restrict__ dl2, const float* __restrict__ dl3,
                  const float* __restrict__ dl4, const float* __restrict__ anchors) {
    extern __shared__ unsigned char sm[];
    u64* cand = (u64*)sm;
    int* misc = (int*)(sm + CAND * 8);
    int tid = threadIdx.x;
    int bl = blockIdx.x, b = bl / NLVL, l = bl % NLVL;
    int h = c_h[l], n = c_n[l], kk = c_k[l], h2 = h * h;

    int S;
    if (l == 4) {
        const float* ob = o4 + (size_t)b * 3 * h2;
        for (int j = tid; j < NPAD; j += 1024) {
            u64 e = 0ULL;
            if (j < n) {
                int p = j / 3, a = j - p * 3, y = p / h, x = p - y * h;
                float v = ob[(a * h + y) * h + x];
                e = ((u64)fkey(v) << 32) | (u32)(~(u32)j);
            }
            cand[j] = e;
        }
        S = 1024;
        __syncthreads();
    } else {
        int m = g_ccnt[bl];
        if (m > CAND) m = CAND;
        S = (m <= 1024) ? 1024 : ((m <= 2048) ? 2048 : 4096);
        for (int q = tid; q < S; q += 1024)
            cand[q] = (q < m) ? g_cand[bl][q] : 0ULL;
        __syncthreads();
    }

    bitonic_desc(cand, S, tid);   // (key desc, idx asc) == lax.top_k order

    float C = 4096.0f * (float)l;
    const float* dl = (l == 0) ? dl0 : (l == 1) ? dl1 : (l == 2) ? dl2 : (l == 3) ? dl3 : dl4;
    int valid = 0;
    float cx1 = 0.f, cy1 = 0.f, cx2 = 0.f, cy2 = 0.f;
    u32 sigbits = 0;
    if (tid < kk) {
        u64 e = cand[tid];
        u32 idx = ~(u32)(e & 0xFFFFFFFFu);
        float logit = unfkey((u32)(e >> 32));
        sigbits = __float_as_uint(__fdiv_rn(1.0f, 1.0f + expf(-logit)));
        int p = (int)(idx / 3u), a = (int)idx - p * 3;
        int y = p / h, x = p - y * h;
        int gi = c_off[l] + (int)idx;
        float ax1 = anchors[4 * gi], ay1 = anchors[4 * gi + 1];
        float ax2 = anchors[4 * gi + 2], ay2 = anchors[4 * gi + 3];
        float wa = ax2 - ax1, ha = ay2 - ay1;
        float cxa = ax1 + 0.5f * wa, cya = ay1 + 0.5f * ha;
        int dbase = ((b * 12 + a * 4) * h + y) * h + x;
        float dx = dl[dbase], dy = dl[dbase + h2];
        float dw = fminf(dl[dbase + 2 * h2], CLIPV);
        float dh = fminf(dl[dbase + 3 * h2], CLIPV);
        float cx = dx * wa + cxa, cy = dy * ha + cya;
        float pw = expf(dw) * wa, ph = expf(dh) * ha;
        cx1 = fminf(fmaxf(cx - 0.5f * pw, 0.0f), IMGSZ);
        cy1 = fminf(fmaxf(cy - 0.5f * ph, 0.0f), IMGSZ);
        cx2 = fminf(fmaxf(cx + 0.5f * pw, 0.0f), IMGSZ);
        cy2 = fminf(fmaxf(cy + 0.5f * ph, 0.0f), IMGSZ);
        valid = ((cx2 - cx1) >= 1e-3f && (cy2 - cy1) >= 1e-3f) ? 1 : 0;
    }
    __syncthreads();

    int nv;
    int vpos = bscan(valid, misc, tid, &nv);
    if (valid) {
        float xo1 = cx1 + C, yo1 = cy1 + C, xo2 = cx2 + C, yo2 = cy2 + C;
        g_obox[bl][vpos] = make_float4(xo1, yo1, xo2, yo2);
        g_oar[bl][vpos] = (xo2 - xo1) * (yo2 - yo1);
        g_ubox[bl][vpos] = make_float4(cx1, cy1, cx2, cy2);
        g_sig[bl][vpos] = sigbits;
    }
    if (tid == 0) g_nv[bl] = nv;
}

// ---- K4: mask builder, full-chip parallel: grid (40, 16) x 256 -----------
__global__ void k_mask() {
    int bl = blockIdx.x, w = blockIdx.y;
    int nv = g_nv[bl];
    int j0 = w << 6;
    if (j0 >= nv) return;
    __shared__ float4 jb[64];
    __shared__ float  ja[64];
    int tid = threadIdx.x;
    int jend = min(j0 + 64, nv);
    if (tid < jend - j0) { jb[tid] = g_obox[bl][j0 + tid]; ja[tid] = g_oar[bl][j0 + tid]; }
    __syncthreads();
    for (int i = tid; i < nv; i += 256) {
        u64 mword = 0;
        int js = max(j0, i + 1) - j0, je = jend - j0;
        if (js < je) {
            float4 bi = g_obox[bl][i];
            float ai = g_oar[bl][i];
            for (int jj = js; jj < je; jj++) {
                float4 bj = jb[jj];
                float lx = fmaxf(bi.x, bj.x), ly = fmaxf(bi.y, bj.y);
                float rx = fminf(bi.z, bj.z), ry = fminf(bi.w, bj.w);
                float ww2 = rx - lx, hh2 = ry - ly;
                if (ww2 > 0.0f && hh2 > 0.0f) {
                    float inter = ww2 * hh2;
                    float uni = ai + ja[jj] - inter + 1e-9f;
                    if (__fdiv_rn(inter, uni) > 0.7f) mword |= 1ULL << jj;
                }
            }
        }
        g_mask[bl][i][w] = mword;
    }
}

// ---- K5: fixed-point greedy NMS + compact --------------------------------
#define SMEM5 (131072 + 512)
__global__ __launch_bounds__(1024, 1)
void k_nms() {
    extern __shared__ unsigned char sm[];
    u64* smask = (u64*)sm;
    u64* cur   = (u64*)(sm + 131072);
    u64* nxt   = cur + 16;
    int* misc  = (int*)(nxt + 16);
    int tid = threadIdx.x, bl = blockIdx.x;
    int nv = g_nv[bl];
    const u64* gm = &g_mask[bl][0][0];
    for (int t = tid; t < nv * 16; t += 1024) smask[t] = gm[t];
    if (tid < 16) cur[tid] = 0ULL;
    __syncthreads();

    int w = tid & 15, i0 = tid >> 4;
    for (int it = 0; it < NPAD; it++) {
        if (tid < 16) nxt[tid] = 0ULL;
        if (tid == 0) misc[0] = 0;
        __syncthreads();
        u64 acc = 0;
        for (int i = i0; i < nv; i += 64)
            if (!((cur[i >> 6] >> (i & 63)) & 1ULL)) acc |= smask[i * 16 + w];
        if (acc) atomicOr(&nxt[w], acc);
        __syncthreads();
        if (tid < 16) {
            if (nxt[tid] != cur[tid]) misc[0] = 1;
            cur[tid] = nxt[tid];
        }
        __syncthreads();
        if (!misc[0]) break;
    }

    int keepf = (tid < nv) && !((cur[tid >> 6] >> (tid & 63)) & 1ULL);
    int ktot;
    int kpos = bscan(keepf, misc + 4, tid, &ktot);
    if (keepf) {
        g_kb[bl][kpos] = g_ubox[bl][tid];
        g_kkey[bl][kpos] = g_sig[bl][tid];
    }
    if (tid == 0) g_kcnt[bl] = ktot;
}

// ---- K6: sortless merge, one block per (b,l) -----------------------------
// rank(l,p,s) = p + sum_{l'<l} #{key' >= s} + sum_{l'>l} #{key' > s}
__global__ __launch_bounds__(1024, 1)
void k_merge(float* __restrict__ out) {
    __shared__ u32 skeys[NLVL][NPAD];
    __shared__ int cnt[NLVL], off[NLVL + 1];
    int bl = blockIdx.x, b = bl / NLVL, l = bl % NLVL;
    int tid = threadIdx.x;
    if (tid < NLVL) cnt[tid] = g_kcnt[b * NLVL + tid];
    __syncthreads();
    if (tid == 0) {
        int s = 0;
        for (int q = 0; q < NLVL; q++) { off[q] = s; s += cnt[q]; }
        off[NLVL] = s;
    }
    __syncthreads();
    int total = off[NLVL];
    for (int l2 = 0; l2 < NLVL; l2++)
        for (int p = tid; p < cnt[l2]; p += 1024)
            skeys[l2][p] = g_kkey[b * NLVL + l2][p];
    __syncthreads();

    if (l == 0)
        for (int j = total + tid; j < 1000; j += 1024)
            ((float4*)out)[b * 1000 + j] = make_float4(0.f, 0.f, 0.f, 0.f);

    int p = tid;
    if (p < cnt[l]) {
        u32 s = skeys[l][p];
        int rank = p;
#pragma unroll
        for (int l2 = 0; l2 < NLVL; l2++) {
            if (l2 == l) continue;
            const u32* a = skeys[l2];
            int lo = 0, hi = cnt[l2];
            if (l2 < l) {
                while (lo < hi) { int mid = (lo + hi) >> 1; if (a[mid] < s) hi = mid; else lo = mid + 1; }
            } else {
                while (lo < hi) { int mid = (lo + hi) >> 1; if (a[mid] <= s) hi = mid; else lo = mid + 1; }
            }
            rank += lo;
        }
        if (rank < 1000)
            ((float4*)out)[b * 1000 + rank] = g_kb[b * NLVL + l][p];
    }
}

static bool msz(const int* s, const int* ref) {
    for (int i = 0; i < 11; i++) if (s[i] != ref[i]) return false;
    return true;
}

extern "C" void kernel_launch(void* const* d_in, const int* in_sizes, int n_in,
                              void* d_out, int out_size) {
    const float *o[5], *dl[5], *anch;
    static const int inter[11] = {960000, 3840000, 240000, 960000, 60000,
                                  240000, 15000, 60000, 4056, 16224, 639528};
    static const int alpha[11] = {639528, 3840000, 960000, 240000, 60000,
                                  16224, 960000, 240000, 60000, 15000, 4056};
    if (n_in >= 11 && msz(in_sizes, inter)) {
        for (int i = 0; i < 5; i++) { o[i] = (const float*)d_in[2 * i]; dl[i] = (const float*)d_in[2 * i + 1]; }
        anch = (const float*)d_in[10];
    } else if (n_in >= 11 && msz(in_sizes, alpha)) {
        anch = (const float*)d_in[0];
        for (int i = 0; i < 5; i++) { dl[i] = (const float*)d_in[1 + i]; o[i] = (const float*)d_in[6 + i]; }
    } else {
        for (int i = 0; i < 5; i++) { o[i] = (const float*)d_in[i]; dl[i] = (const float*)d_in[5 + i]; }
        anch = (const float*)d_in[10];
    }
    (void)out_size;

    static int attr_done = 0;
    if (!attr_done) {
        cudaFuncSetAttribute(k_nms, cudaFuncAttributeMaxDynamicSharedMemorySize, SMEM5);
        attr_done = 1;
    }

    k_hist<<<dim3(NBL, NCH), 256>>>(o[0], o[1], o[2], o[3]);
    k_thresh<<<NBL, 1024>>>();
    k_compact<<<dim3(NBL, NCH), 256>>>(o[0], o[1], o[2], o[3]);
    k_sortdecode<<<NBL, 1024, SMEM3>>>(o[4], dl[0], dl[1], dl[2], dl[3], dl[4], anch);
    k_mask<<<dim3(NBL, 16), 256>>>();
    k_nms<<<NBL, 1024, SMEM5>>>();
    k_merge<<<NBL, 1024>>>((float*)d_out);
}